// round 16
// baseline (speedup 1.0000x reference)
#include <cuda_runtime.h>
#include <cuda_fp16.h>
#include <stdint.h>
#include <math.h>

// ============================================================
// ROUND 16: fuse gate + fp16 conversion into one prep_kernel
// (fusion read ONCE; gate_W cached in smem — kills ~786MB of
// L2 re-reads). GEMMs identical to R15 (fp16 mma.sync m16n8k16).
// GB300 ATS rule: no __device__ symbol passed from host.
// ============================================================

#define NB   16384
#define DD   512
#define NL   6
#define NCLS 3992
#define NE   4

#define BM 128
#define BN 128
#define BK 64
#define RSTRB 144
#define RSTR2 36
#define TILE_BYTES (BM * RSTRB)
#define STG_B (2 * TILE_BYTES)
#define SMEM_BYTES (2 * STG_B)

// -------- device scratch --------
__device__ __half g_xh[NL * NB * DD];
__device__ __half g_h [NB * DD];
__device__ __half g_s [NB * DD];
__device__ __half g_td[NB * DD];
__device__ float  g_mean[4096];
__device__ __half g_w1t0[512 * 1536];
__device__ __half g_w1t1[512 * 1536];
__device__ __half g_w1t2[512 * 3072];
__device__ __half g_w1t3[512 * 3072];
__device__ __half g_w2t0[512 * 512];
__device__ __half g_w2t1[512 * 512];
__device__ __half g_w2t2[512 * 512];
__device__ __half g_w2t3[512 * 512];
__device__ __half g_d1t [512 * 512];
__device__ __half g_d2t [4096 * 512];
__device__ int    g_sel[NB];
__device__ int    g_rows[NE * NB];
__device__ int    g_cnt[NE];

__device__ __forceinline__ uint32_t s2u(const void* p) {
    uint32_t a;
    asm("{ .reg .u64 t; cvta.to.shared.u64 t, %1; cvt.u32.u64 %0, t; }"
        : "=r"(a) : "l"(p));
    return a;
}
__device__ __forceinline__ void cp16(uint32_t dst, const void* src, int srcsz) {
    asm volatile("cp.async.cg.shared.global [%0], [%1], 16, %2;"
                 :: "r"(dst), "l"(src), "r"(srcsz));
}
__device__ __forceinline__ void cp_commit() { asm volatile("cp.async.commit_group;"); }
__device__ __forceinline__ void cp_wait0()  { asm volatile("cp.async.wait_group 0;" ::: "memory"); }

#define MMA_F16(c, a, b)                                                     \
    asm("mma.sync.aligned.m16n8k16.row.col.f32.f16.f16.f32 "                 \
        "{%0,%1,%2,%3}, {%4,%5,%6,%7}, {%8,%9}, {%0,%1,%2,%3};"              \
        : "+f"((c)[0]), "+f"((c)[1]), "+f"((c)[2]), "+f"((c)[3])             \
        : "r"((a)[0]), "r"((a)[1]), "r"((a)[2]), "r"((a)[3]),                \
          "r"((b)[0]), "r"((b)[1]))

__device__ __forceinline__ void tile_mma(const char* As, const char* Bs,
                                         float acc[2][8][4],
                                         int warpM, int warpN, int g, int tg) {
    const unsigned* Au = (const unsigned*)As;
    const unsigned* Bu = (const unsigned*)Bs;
#pragma unroll
    for (int ks = 0; ks < 4; ks++) {
        unsigned a[2][4], b[8][2];
#pragma unroll
        for (int mi = 0; mi < 2; mi++) {
            int r0 = warpM + mi * 16 + g;
            a[mi][0] = Au[r0 * RSTR2 + ks * 8 + tg];
            a[mi][1] = Au[(r0 + 8) * RSTR2 + ks * 8 + tg];
            a[mi][2] = Au[r0 * RSTR2 + ks * 8 + tg + 4];
            a[mi][3] = Au[(r0 + 8) * RSTR2 + ks * 8 + tg + 4];
        }
#pragma unroll
        for (int ni = 0; ni < 8; ni++) {
            int n = warpN + ni * 8 + g;
            b[ni][0] = Bu[n * RSTR2 + ks * 8 + tg];
            b[ni][1] = Bu[n * RSTR2 + ks * 8 + tg + 4];
        }
#pragma unroll
        for (int mi = 0; mi < 2; mi++)
#pragma unroll
            for (int ni = 0; ni < 8; ni++)
                MMA_F16(acc[mi][ni], a[mi], b[ni]);
    }
}

// ============================================================
// K0: prep — fused fp16 conversion + gate logits/argmax.
// 256 blocks x 256 threads; each block: gate_W in smem (48KB),
// 64 rows, one fusion read total. Gate math exact fp32,
// deterministic fixed-order reduction.
// ============================================================
__global__ __launch_bounds__(256) void prep_kernel(const float* __restrict__ fusion,
                                                   const float* __restrict__ gW,
                                                   const float* __restrict__ gb) {
    __shared__ float sW[NL * DD * NE];   // 3072*4 floats = 48KB
    int tid = threadIdx.x;
    for (int i = tid; i < NL * DD; i += 256) {
        float4 w = *(const float4*)(gW + (size_t)i * 4);
        *(float4*)(sW + (size_t)i * 4) = w;
    }
    __syncthreads();

    int warp = tid >> 5, lane = tid & 31;
    float gb0 = gb[0], gb1 = gb[1], gb2 = gb[2], gb3 = gb[3];

    int rbase = blockIdx.x * 64 + warp * 8;
#pragma unroll 1
    for (int i = 0; i < 8; i++) {
        int b = rbase + i;
        float a0 = 0.f, a1 = 0.f, a2 = 0.f, a3 = 0.f;
#pragma unroll
        for (int l = 0; l < NL; l++) {
            const float* rowp = fusion + ((size_t)l * NB + b) * DD;
            __half2* dstp = (__half2*)(g_xh + ((size_t)l * NB + b) * DD);
#pragma unroll
            for (int j = 0; j < 4; j++) {
                int i4 = lane + 32 * j;
                float4 x = *(const float4*)(rowp + i4 * 4);
                dstp[i4 * 2 + 0] = __floats2half2_rn(x.x, x.y);
                dstp[i4 * 2 + 1] = __floats2half2_rn(x.z, x.w);
                int k = l * DD + i4 * 4;
                float4 w0 = *(const float4*)(sW + (size_t)(k + 0) * 4);
                float4 w1 = *(const float4*)(sW + (size_t)(k + 1) * 4);
                float4 w2 = *(const float4*)(sW + (size_t)(k + 2) * 4);
                float4 w3 = *(const float4*)(sW + (size_t)(k + 3) * 4);
                a0 += x.x * w0.x + x.y * w1.x + x.z * w2.x + x.w * w3.x;
                a1 += x.x * w0.y + x.y * w1.y + x.z * w2.y + x.w * w3.y;
                a2 += x.x * w0.z + x.y * w1.z + x.z * w2.z + x.w * w3.z;
                a3 += x.x * w0.w + x.y * w1.w + x.z * w2.w + x.w * w3.w;
            }
        }
#pragma unroll
        for (int o = 16; o; o >>= 1) {
            a0 += __shfl_down_sync(0xffffffffu, a0, o);
            a1 += __shfl_down_sync(0xffffffffu, a1, o);
            a2 += __shfl_down_sync(0xffffffffu, a2, o);
            a3 += __shfl_down_sync(0xffffffffu, a3, o);
        }
        if (lane == 0) {
            a0 += gb0; a1 += gb1; a2 += gb2; a3 += gb3;
            int bi = 0; float best = a0;
            if (a1 > best) { best = a1; bi = 1; }
            if (a2 > best) { best = a2; bi = 2; }
            if (a3 > best) { best = a3; bi = 3; }
            g_sel[b] = bi;
        }
    }
}

__global__ void zero_cnt_kernel() {
    if (threadIdx.x < NE) g_cnt[threadIdx.x] = 0;
}
__global__ void compact_kernel() {
    int b = blockIdx.x * blockDim.x + threadIdx.x;
    if (b < NB) {
        int e = g_sel[b];
        int i = atomicAdd(&g_cnt[e], 1);
        g_rows[e * NB + i] = b;
    }
}

// transpose: dst[n*K+k] = fp16(src[k*N+n]) (optional per-k scale for e3)
__global__ void transpose_kernel(const float* __restrict__ src, __half* __restrict__ dst,
                                 int K, int N, int Npad,
                                 const float* pa, const float* pb, int ksplit) {
    __shared__ float t[32][33];
    int bn = blockIdx.x * 32, bk = blockIdx.y * 32;
    int x = threadIdx.x, y = threadIdx.y;
#pragma unroll
    for (int j = 0; j < 32; j += 8) {
        int k = bk + y + j, n = bn + x;
        float v = (k < K && n < N) ? src[(size_t)k * N + n] : 0.f;
        if (pa) v *= (k < ksplit ? *pa : *pb);
        t[y + j][x] = v;
    }
    __syncthreads();
#pragma unroll
    for (int j = 0; j < 32; j += 8) {
        int n = bn + y + j, k = bk + x;
        if (n < Npad && k < K) dst[(size_t)n * K + k] = __float2half_rn(t[x][y + j]);
    }
}

__global__ void mean_init_kernel(const float* __restrict__ b) {
    int c = blockIdx.x * blockDim.x + threadIdx.x;
    if (c < NCLS) g_mean[c] = b[c];
}
__global__ void mean_part_kernel(const float* __restrict__ W) {
    int c = blockIdx.x * blockDim.x + threadIdx.x;
    if (c >= NCLS) return;
    int k0 = blockIdx.y * 64;
    float s = 0.f;
#pragma unroll 8
    for (int k = k0; k < k0 + 64; k++) s += W[(size_t)k * NCLS + c];
    atomicAdd(&g_mean[c], 0.5f * s);
}

// ============================================================
// K2: routed expert layer1 (fp16 MMA)
// ============================================================
__global__ __launch_bounds__(256) void expert1_h(
    const float* b10, const float* b11, const float* b12, const float* b13) {

    extern __shared__ char smem[];
    int e = blockIdx.z;
    int cnt = g_cnt[e];
    int row0 = blockIdx.x * BM;
    if (row0 >= cnt) return;

    int seg = 0;
#pragma unroll
    for (int q = 0; q < NE; q++) if (q < e) seg += g_cnt[q];

    const __half* Bts[4] = { g_w1t0, g_w1t1, g_w1t2, g_w1t3 };
    const float*  b1s[4] = { b10, b11, b12, b13 };
    const int     Ks[4]  = { 1536, 1536, 3072, 3072 };
    const int     Bs_[4] = { 0, 3, 0, 0 };
    const __half* Bt = Bts[e];
    const float*  b1 = b1s[e];
    int K = Ks[e];
    int base = Bs_[e];

    __shared__ int rowids[BM];
    int tid = threadIdx.x;
    for (int i = tid; i < BM; i += 256) {
        int r = row0 + i;
        rowids[i] = (r < cnt) ? g_rows[e * NB + r] : -1;
    }
    __syncthreads();

    int col0 = blockIdx.y * BN;
    int wid = tid >> 5, lane = tid & 31, g = lane >> 2, tg = lane & 3;
    int warpM = (wid & 3) * 32, warpN = (wid >> 2) * 64;
    int lr = tid >> 3, lc = tid & 7;

    float acc[2][8][4];
#pragma unroll
    for (int mi = 0; mi < 2; mi++)
#pragma unroll
        for (int ni = 0; ni < 8; ni++)
#pragma unroll
            for (int k = 0; k < 4; k++) acc[mi][ni][k] = 0.f;

    int ntiles = K / BK;

    auto prefetch = [&](int it) {
        int kc = it * BK;
        uint32_t sb = s2u(smem) + (it & 1) * STG_B;
#pragma unroll
        for (int t = 0; t < 4; t++) {
            int r = lr + t * 32;
            int rid = rowids[r];
            int kg = kc + lc * 8;
            int lraw = kg >> 9, d = kg & 511;
            const __half* src = g_xh + ((size_t)(lraw + base) * NB + (rid < 0 ? 0 : rid)) * DD + d;
            cp16(sb + r * RSTRB + lc * 16, src, rid >= 0 ? 16 : 0);
        }
#pragma unroll
        for (int t = 0; t < 4; t++) {
            int n = lr + t * 32;
            cp16(sb + TILE_BYTES + n * RSTRB + lc * 16,
                 Bt + (size_t)(col0 + n) * K + kc + lc * 8, 16);
        }
        cp_commit();
    };

    prefetch(0);
    for (int it = 0; it < ntiles; it++) {
        cp_wait0();
        __syncthreads();
        if (it + 1 < ntiles) prefetch(it + 1);
        const char* Ac = smem + (it & 1) * STG_B;
        tile_mma(Ac, Ac + TILE_BYTES, acc, warpM, warpN, g, tg);
        __syncthreads();
    }

#pragma unroll
    for (int mi = 0; mi < 2; mi++) {
        int ra = row0 + warpM + mi * 16 + g;
        int rb = ra + 8;
#pragma unroll
        for (int ni = 0; ni < 8; ni++) {
            int c0 = col0 + warpN + ni * 8 + tg * 2;
            float bb0 = b1[c0], bb1 = b1[c0 + 1];
            if (ra < cnt) {
                __half2 h = __floats2half2_rn(fmaxf(acc[mi][ni][0] + bb0, 0.f),
                                              fmaxf(acc[mi][ni][1] + bb1, 0.f));
                *(__half2*)(g_h + (size_t)(seg + ra) * DD + c0) = h;
            }
            if (rb < cnt) {
                __half2 h = __floats2half2_rn(fmaxf(acc[mi][ni][2] + bb0, 0.f),
                                              fmaxf(acc[mi][ni][3] + bb1, 0.f));
                *(__half2*)(g_h + (size_t)(seg + rb) * DD + c0) = h;
            }
        }
    }
}

// ============================================================
// K3: routed expert layer2 (fp16 MMA); scatter fp16 to g_s
// ============================================================
__global__ __launch_bounds__(256) void expert2_h(
    const float* b20, const float* b21, const float* b22, const float* b23) {

    extern __shared__ char smem[];
    int e = blockIdx.z;
    int cnt = g_cnt[e];
    int row0 = blockIdx.x * BM;
    if (row0 >= cnt) return;

    int seg = 0;
#pragma unroll
    for (int q = 0; q < NE; q++) if (q < e) seg += g_cnt[q];

    const __half* Bts[4] = { g_w2t0, g_w2t1, g_w2t2, g_w2t3 };
    const float*  b2s[4] = { b20, b21, b22, b23 };
    const __half* Bt = Bts[e];
    const float*  b2 = b2s[e];
    const int K = DD;

    __shared__ int rowids[BM];
    int tid = threadIdx.x;
    for (int i = tid; i < BM; i += 256) {
        int r = row0 + i;
        rowids[i] = (r < cnt) ? g_rows[e * NB + r] : -1;
    }
    __syncthreads();

    int col0 = blockIdx.y * BN;
    int wid = tid >> 5, lane = tid & 31, g = lane >> 2, tg = lane & 3;
    int warpM = (wid & 3) * 32, warpN = (wid >> 2) * 64;
    int lr = tid >> 3, lc = tid & 7;

    float acc[2][8][4];
#pragma unroll
    for (int mi = 0; mi < 2; mi++)
#pragma unroll
        for (int ni = 0; ni < 8; ni++)
#pragma unroll
            for (int k = 0; k < 4; k++) acc[mi][ni][k] = 0.f;

    const int ntiles = K / BK;

    auto prefetch = [&](int it) {
        int kc = it * BK;
        uint32_t sb = s2u(smem) + (it & 1) * STG_B;
#pragma unroll
        for (int t = 0; t < 4; t++) {
            int r = lr + t * 32;
            int ok = (row0 + r < cnt);
            cp16(sb + r * RSTRB + lc * 16,
                 g_h + (size_t)(seg + row0 + r) * DD + kc + lc * 8, ok ? 16 : 0);
        }
#pragma unroll
        for (int t = 0; t < 4; t++) {
            int n = lr + t * 32;
            cp16(sb + TILE_BYTES + n * RSTRB + lc * 16,
                 Bt + (size_t)(col0 + n) * K + kc + lc * 8, 16);
        }
        cp_commit();
    };

    prefetch(0);
    for (int it = 0; it < ntiles; it++) {
        cp_wait0();
        __syncthreads();
        if (it + 1 < ntiles) prefetch(it + 1);
        const char* Ac = smem + (it & 1) * STG_B;
        tile_mma(Ac, Ac + TILE_BYTES, acc, warpM, warpN, g, tg);
        __syncthreads();
    }

#pragma unroll
    for (int mi = 0; mi < 2; mi++) {
        int la = warpM + mi * 16 + g;
        int lb = la + 8;
        int rowa = rowids[la];
        int rowb = rowids[lb];
#pragma unroll
        for (int ni = 0; ni < 8; ni++) {
            int c0 = col0 + warpN + ni * 8 + tg * 2;
            float bb0 = b2[c0], bb1 = b2[c0 + 1];
            if (rowa >= 0) {
                __half2 h = __floats2half2_rn(acc[mi][ni][0] + bb0, acc[mi][ni][1] + bb1);
                *(__half2*)(g_s + (size_t)rowa * DD + c0) = h;
            }
            if (rowb >= 0) {
                __half2 h = __floats2half2_rn(acc[mi][ni][2] + bb0, acc[mi][ni][3] + bb1);
                *(__half2*)(g_s + (size_t)rowb * DD + c0) = h;
            }
        }
    }
}

// ============================================================
// K4: decoder layer1 (fp16 MMA); g_td = fp16(sigmoid-0.5)
// ============================================================
__global__ __launch_bounds__(256) void dec1_h(const float* __restrict__ bias) {
    extern __shared__ char smem[];
    int row0 = blockIdx.x * BM;
    int col0 = blockIdx.y * BN;
    int tid = threadIdx.x;
    int wid = tid >> 5, lane = tid & 31, g = lane >> 2, tg = lane & 3;
    int warpM = (wid & 3) * 32, warpN = (wid >> 2) * 64;
    int lr = tid >> 3, lc = tid & 7;

    float acc[2][8][4];
#pragma unroll
    for (int mi = 0; mi < 2; mi++)
#pragma unroll
        for (int ni = 0; ni < 8; ni++)
#pragma unroll
            for (int k = 0; k < 4; k++) acc[mi][ni][k] = 0.f;

    const int ntiles = DD / BK;

    auto prefetch = [&](int it) {
        int kc = it * BK;
        uint32_t sb = s2u(smem) + (it & 1) * STG_B;
#pragma unroll
        for (int t = 0; t < 4; t++) {
            int r = lr + t * 32;
            cp16(sb + r * RSTRB + lc * 16,
                 g_s + (size_t)(row0 + r) * DD + kc + lc * 8, 16);
        }
#pragma unroll
        for (int t = 0; t < 4; t++) {
            int n = lr + t * 32;
            cp16(sb + TILE_BYTES + n * RSTRB + lc * 16,
                 g_d1t + (size_t)(col0 + n) * DD + kc + lc * 8, 16);
        }
        cp_commit();
    };

    prefetch(0);
    for (int it = 0; it < ntiles; it++) {
        cp_wait0();
        __syncthreads();
        if (it + 1 < ntiles) prefetch(it + 1);
        const char* Ac = smem + (it & 1) * STG_B;
        tile_mma(Ac, Ac + TILE_BYTES, acc, warpM, warpN, g, tg);
        __syncthreads();
    }

#pragma unroll
    for (int mi = 0; mi < 2; mi++) {
        int ra = row0 + warpM + mi * 16 + g;
        int rb = ra + 8;
#pragma unroll
        for (int ni = 0; ni < 8; ni++) {
            int c0 = col0 + warpN + ni * 8 + tg * 2;
            float bb0 = bias[c0], bb1 = bias[c0 + 1];
            float z0 = 1.f / (1.f + expf(-(acc[mi][ni][0] + bb0))) - 0.5f;
            float z1 = 1.f / (1.f + expf(-(acc[mi][ni][1] + bb1))) - 0.5f;
            float z2 = 1.f / (1.f + expf(-(acc[mi][ni][2] + bb0))) - 0.5f;
            float z3 = 1.f / (1.f + expf(-(acc[mi][ni][3] + bb1))) - 0.5f;
            *(__half2*)(g_td + (size_t)ra * DD + c0) = __floats2half2_rn(z0, z1);
            *(__half2*)(g_td + (size_t)rb * DD + c0) = __floats2half2_rn(z2, z3);
        }
    }
}

// ============================================================
// K5: decoder layer2 (fp16 MMA) on delta; out = acc + mean[c]
// ============================================================
__global__ __launch_bounds__(256) void dec2_h(float* __restrict__ out) {
    extern __shared__ char smem[];
    int row0 = blockIdx.x * BM;
    int col0 = blockIdx.y * BN;
    int tid = threadIdx.x;
    int wid = tid >> 5, lane = tid & 31, g = lane >> 2, tg = lane & 3;
    int warpM = (wid & 3) * 32, warpN = (wid >> 2) * 64;
    int lr = tid >> 3, lc = tid & 7;

    float acc[2][8][4];
#pragma unroll
    for (int mi = 0; mi < 2; mi++)
#pragma unroll
        for (int ni = 0; ni < 8; ni++)
#pragma unroll
            for (int k = 0; k < 4; k++) acc[mi][ni][k] = 0.f;

    const int ntiles = DD / BK;

    auto prefetch = [&](int it) {
        int kc = it * BK;
        uint32_t sb = s2u(smem) + (it & 1) * STG_B;
#pragma unroll
        for (int t = 0; t < 4; t++) {
            int r = lr + t * 32;
            cp16(sb + r * RSTRB + lc * 16,
                 g_td + (size_t)(row0 + r) * DD + kc + lc * 8, 16);
        }
#pragma unroll
        for (int t = 0; t < 4; t++) {
            int n = lr + t * 32;
            cp16(sb + TILE_BYTES + n * RSTRB + lc * 16,
                 g_d2t + (size_t)(col0 + n) * DD + kc + lc * 8, 16);
        }
        cp_commit();
    };

    prefetch(0);
    for (int it = 0; it < ntiles; it++) {
        cp_wait0();
        __syncthreads();
        if (it + 1 < ntiles) prefetch(it + 1);
        const char* Ac = smem + (it & 1) * STG_B;
        tile_mma(Ac, Ac + TILE_BYTES, acc, warpM, warpN, g, tg);
        __syncthreads();
    }

#pragma unroll
    for (int mi = 0; mi < 2; mi++) {
        int ra = row0 + warpM + mi * 16 + g;
        int rb = ra + 8;
#pragma unroll
        for (int ni = 0; ni < 8; ni++) {
            int c0 = col0 + warpN + ni * 8 + tg * 2;
            int c1 = c0 + 1;
            if (c0 < NCLS) {
                float m0 = g_mean[c0];
                out[(size_t)ra * NCLS + c0] = acc[mi][ni][0] + m0;
                out[(size_t)rb * NCLS + c0] = acc[mi][ni][2] + m0;
            }
            if (c1 < NCLS) {
                float m1 = g_mean[c1];
                out[(size_t)ra * NCLS + c1] = acc[mi][ni][1] + m1;
                out[(size_t)rb * NCLS + c1] = acc[mi][ni][3] + m1;
            }
        }
    }
}

// ============================================================
// launch
// ============================================================
extern "C" void kernel_launch(void* const* d_in, const int* in_sizes, int n_in,
                              void* d_out, int out_size) {
    const float* fusion = (const float*)d_in[0];
    const float* gate_W = (const float*)d_in[1];
    const float* gate_b = (const float*)d_in[2];
    const float* e0_W1  = (const float*)d_in[3];
    const float* e0_b1  = (const float*)d_in[4];
    const float* e0_W2  = (const float*)d_in[5];
    const float* e0_b2  = (const float*)d_in[6];
    const float* e1_W1  = (const float*)d_in[7];
    const float* e1_b1  = (const float*)d_in[8];
    const float* e1_W2  = (const float*)d_in[9];
    const float* e1_b2  = (const float*)d_in[10];
    const float* e2_W1  = (const float*)d_in[11];
    const float* e2_b1  = (const float*)d_in[12];
    const float* e2_W2  = (const float*)d_in[13];
    const float* e2_b2  = (const float*)d_in[14];
    const float* e3_W1  = (const float*)d_in[15];
    const float* e3_b1  = (const float*)d_in[16];
    const float* e3_W2  = (const float*)d_in[17];
    const float* e3_b2  = (const float*)d_in[18];
    const float* e3_a   = (const float*)d_in[19];
    const float* e3_b   = (const float*)d_in[20];
    const float* dec_W1 = (const float*)d_in[21];
    const float* dec_b1 = (const float*)d_in[22];
    const float* dec_W2 = (const float*)d_in[23];
    const float* dec_b2 = (const float*)d_in[24];
    float* out = (float*)d_out;

    static bool attr_done = false;
    if (!attr_done) {
        cudaFuncSetAttribute(expert1_h, cudaFuncAttributeMaxDynamicSharedMemorySize, SMEM_BYTES);
        cudaFuncSetAttribute(expert2_h, cudaFuncAttributeMaxDynamicSharedMemorySize, SMEM_BYTES);
        cudaFuncSetAttribute(dec1_h,    cudaFuncAttributeMaxDynamicSharedMemorySize, SMEM_BYTES);
        cudaFuncSetAttribute(dec2_h,    cudaFuncAttributeMaxDynamicSharedMemorySize, SMEM_BYTES);
        attr_done = true;
    }

    // K0: fused gate + fp16 conversion (fusion read once)
    prep_kernel<<<NB / 64, 256>>>(fusion, gate_W, gate_b);

    zero_cnt_kernel<<<1, 32>>>();
    compact_kernel<<<NB / 256, 256>>>();

    // weight transposes -> fp16 [N][K]
    {
        dim3 blk(32, 8);
        __half* w1t0; cudaGetSymbolAddress((void**)&w1t0, g_w1t0);
        __half* w1t1; cudaGetSymbolAddress((void**)&w1t1, g_w1t1);
        __half* w1t2; cudaGetSymbolAddress((void**)&w1t2, g_w1t2);
        __half* w1t3; cudaGetSymbolAddress((void**)&w1t3, g_w1t3);
        __half* w2t0; cudaGetSymbolAddress((void**)&w2t0, g_w2t0);
        __half* w2t1; cudaGetSymbolAddress((void**)&w2t1, g_w2t1);
        __half* w2t2; cudaGetSymbolAddress((void**)&w2t2, g_w2t2);
        __half* w2t3; cudaGetSymbolAddress((void**)&w2t3, g_w2t3);
        __half* d1t;  cudaGetSymbolAddress((void**)&d1t,  g_d1t);
        __half* d2t;  cudaGetSymbolAddress((void**)&d2t,  g_d2t);

        transpose_kernel<<<dim3(16, 48), blk>>>(e0_W1, w1t0, 1536, 512, 512, 0, 0, 0);
        transpose_kernel<<<dim3(16, 48), blk>>>(e1_W1, w1t1, 1536, 512, 512, 0, 0, 0);
        transpose_kernel<<<dim3(16, 96), blk>>>(e2_W1, w1t2, 3072, 512, 512, 0, 0, 0);
        transpose_kernel<<<dim3(16, 96), blk>>>(e3_W1, w1t3, 3072, 512, 512, e3_a, e3_b, 1536);
        transpose_kernel<<<dim3(16, 16), blk>>>(e0_W2, w2t0, 512, 512, 512, 0, 0, 0);
        transpose_kernel<<<dim3(16, 16), blk>>>(e1_W2, w2t1, 512, 512, 512, 0, 0, 0);
        transpose_kernel<<<dim3(16, 16), blk>>>(e2_W2, w2t2, 512, 512, 512, 0, 0, 0);
        transpose_kernel<<<dim3(16, 16), blk>>>(e3_W2, w2t3, 512, 512, 512, 0, 0, 0);
        transpose_kernel<<<dim3(16, 16), blk>>>(dec_W1, d1t, 512, 512, 512, 0, 0, 0);
        transpose_kernel<<<dim3(128, 16), blk>>>(dec_W2, d2t, 512, 3992, 4096, 0, 0, 0);
    }

    mean_init_kernel<<<(NCLS + 255) / 256, 256>>>(dec_b2);
    {
        dim3 grid((NCLS + 255) / 256, DD / 64);
        mean_part_kernel<<<grid, 256>>>(dec_W2);
    }

    {
        dim3 grid(NB / BM, DD / BN, NE);
        expert1_h<<<grid, 256, SMEM_BYTES>>>(e0_b1, e1_b1, e2_b1, e3_b1);
    }
    {
        dim3 grid(NB / BM, DD / BN, NE);
        expert2_h<<<grid, 256, SMEM_BYTES>>>(e0_b2, e1_b2, e2_b2, e3_b2);
    }
    {
        dim3 grid(NB / BM, DD / BN);
        dec1_h<<<grid, 256, SMEM_BYTES>>>(dec_b1);
    }
    {
        dim3 grid(NB / BM, (NCLS + BN - 1) / BN);
        dec2_h<<<grid, 256, SMEM_BYTES>>>(out);
    }
}

// round 17
// speedup vs baseline: 1.0572x; 1.0572x over previous
#include <cuda_runtime.h>
#include <cuda_fp16.h>
#include <stdint.h>
#include <math.h>

// ============================================================
// ROUND 17: R15 kernels (separate gate/conv — R16 fusion reverted)
// + fork-join stream parallelism for the prep stage:
//   stream0: gate -> compact -> [join A,B] experts -> [join C] dec
//   sA: fp16 conv ; sB: expert-W transposes ; sC: dec transposes+mean
// (streams/events created on first uncaptured call; record/wait
//  during capture builds parallel graph branches)
// GB300 ATS rule: no __device__ symbol passed from host.
// ============================================================

#define NB   16384
#define DD   512
#define NL   6
#define NCLS 3992
#define NE   4

#define BM 128
#define BN 128
#define BK 64
#define RSTRB 144
#define RSTR2 36
#define TILE_BYTES (BM * RSTRB)
#define STG_B (2 * TILE_BYTES)
#define SMEM_BYTES (2 * STG_B)

// -------- device scratch --------
__device__ __half g_xh[NL * NB * DD];
__device__ __half g_h [NB * DD];
__device__ __half g_s [NB * DD];
__device__ __half g_td[NB * DD];
__device__ float  g_mean[4096];
__device__ __half g_w1t0[512 * 1536];
__device__ __half g_w1t1[512 * 1536];
__device__ __half g_w1t2[512 * 3072];
__device__ __half g_w1t3[512 * 3072];
__device__ __half g_w2t0[512 * 512];
__device__ __half g_w2t1[512 * 512];
__device__ __half g_w2t2[512 * 512];
__device__ __half g_w2t3[512 * 512];
__device__ __half g_d1t [512 * 512];
__device__ __half g_d2t [4096 * 512];
__device__ int    g_sel[NB];
__device__ int    g_rows[NE * NB];
__device__ int    g_cnt[NE];

__device__ __forceinline__ uint32_t s2u(const void* p) {
    uint32_t a;
    asm("{ .reg .u64 t; cvta.to.shared.u64 t, %1; cvt.u32.u64 %0, t; }"
        : "=r"(a) : "l"(p));
    return a;
}
__device__ __forceinline__ void cp16(uint32_t dst, const void* src, int srcsz) {
    asm volatile("cp.async.cg.shared.global [%0], [%1], 16, %2;"
                 :: "r"(dst), "l"(src), "r"(srcsz));
}
__device__ __forceinline__ void cp_commit() { asm volatile("cp.async.commit_group;"); }
__device__ __forceinline__ void cp_wait0()  { asm volatile("cp.async.wait_group 0;" ::: "memory"); }

#define MMA_F16(c, a, b)                                                     \
    asm("mma.sync.aligned.m16n8k16.row.col.f32.f16.f16.f32 "                 \
        "{%0,%1,%2,%3}, {%4,%5,%6,%7}, {%8,%9}, {%0,%1,%2,%3};"              \
        : "+f"((c)[0]), "+f"((c)[1]), "+f"((c)[2]), "+f"((c)[3])             \
        : "r"((a)[0]), "r"((a)[1]), "r"((a)[2]), "r"((a)[3]),                \
          "r"((b)[0]), "r"((b)[1]))

__device__ __forceinline__ void tile_mma(const char* As, const char* Bs,
                                         float acc[2][8][4],
                                         int warpM, int warpN, int g, int tg) {
    const unsigned* Au = (const unsigned*)As;
    const unsigned* Bu = (const unsigned*)Bs;
#pragma unroll
    for (int ks = 0; ks < 4; ks++) {
        unsigned a[2][4], b[8][2];
#pragma unroll
        for (int mi = 0; mi < 2; mi++) {
            int r0 = warpM + mi * 16 + g;
            a[mi][0] = Au[r0 * RSTR2 + ks * 8 + tg];
            a[mi][1] = Au[(r0 + 8) * RSTR2 + ks * 8 + tg];
            a[mi][2] = Au[r0 * RSTR2 + ks * 8 + tg + 4];
            a[mi][3] = Au[(r0 + 8) * RSTR2 + ks * 8 + tg + 4];
        }
#pragma unroll
        for (int ni = 0; ni < 8; ni++) {
            int n = warpN + ni * 8 + g;
            b[ni][0] = Bu[n * RSTR2 + ks * 8 + tg];
            b[ni][1] = Bu[n * RSTR2 + ks * 8 + tg + 4];
        }
#pragma unroll
        for (int mi = 0; mi < 2; mi++)
#pragma unroll
            for (int ni = 0; ni < 8; ni++)
                MMA_F16(acc[mi][ni], a[mi], b[ni]);
    }
}

// ============================================================
// K1: gate logits + argmax (one warp per row), exact fp32
// ============================================================
__global__ __launch_bounds__(128) void gate_kernel(const float* __restrict__ fusion,
                                                   const float* __restrict__ gW,
                                                   const float* __restrict__ gb) {
    int warp = blockIdx.x * (blockDim.x >> 5) + (threadIdx.x >> 5);
    int lane = threadIdx.x & 31;
    if (warp >= NB) return;
    int b = warp;
    float a0 = 0.f, a1 = 0.f, a2 = 0.f, a3 = 0.f;
    for (int i4 = lane; i4 < (NL * DD) / 4; i4 += 32) {
        int kk = i4 * 4;
        int l = kk >> 9, d = kk & 511;
        float4 x = *(const float4*)(fusion + ((size_t)l * NB + b) * DD + d);
        float4 w0 = *(const float4*)(gW + (size_t)(kk + 0) * 4);
        float4 w1 = *(const float4*)(gW + (size_t)(kk + 1) * 4);
        float4 w2 = *(const float4*)(gW + (size_t)(kk + 2) * 4);
        float4 w3 = *(const float4*)(gW + (size_t)(kk + 3) * 4);
        a0 += x.x * w0.x + x.y * w1.x + x.z * w2.x + x.w * w3.x;
        a1 += x.x * w0.y + x.y * w1.y + x.z * w2.y + x.w * w3.y;
        a2 += x.x * w0.z + x.y * w1.z + x.z * w2.z + x.w * w3.z;
        a3 += x.x * w0.w + x.y * w1.w + x.z * w2.w + x.w * w3.w;
    }
#pragma unroll
    for (int o = 16; o; o >>= 1) {
        a0 += __shfl_down_sync(0xffffffffu, a0, o);
        a1 += __shfl_down_sync(0xffffffffu, a1, o);
        a2 += __shfl_down_sync(0xffffffffu, a2, o);
        a3 += __shfl_down_sync(0xffffffffu, a3, o);
    }
    if (lane == 0) {
        a0 += gb[0]; a1 += gb[1]; a2 += gb[2]; a3 += gb[3];
        int bi = 0; float best = a0;
        if (a1 > best) { best = a1; bi = 1; }
        if (a2 > best) { best = a2; bi = 2; }
        if (a3 > best) { best = a3; bi = 3; }
        g_sel[b] = bi;
    }
}

__global__ void zero_cnt_kernel() {
    if (threadIdx.x < NE) g_cnt[threadIdx.x] = 0;
}
__global__ void compact_kernel() {
    int b = blockIdx.x * blockDim.x + threadIdx.x;
    if (b < NB) {
        int e = g_sel[b];
        int i = atomicAdd(&g_cnt[e], 1);
        g_rows[e * NB + i] = b;
    }
}

// convert fusion f32 -> fp16 scratch (RNE)
__global__ void conv_fusion_kernel(const float* __restrict__ src) {
    size_t i = (size_t)blockIdx.x * blockDim.x + threadIdx.x;
    float4 v = ((const float4*)src)[i];
    __half2* dst = (__half2*)g_xh;
    dst[i * 2 + 0] = __floats2half2_rn(v.x, v.y);
    dst[i * 2 + 1] = __floats2half2_rn(v.z, v.w);
}

// transpose: dst[n*K+k] = fp16(src[k*N+n]) (optional per-k scale for e3)
__global__ void transpose_kernel(const float* __restrict__ src, __half* __restrict__ dst,
                                 int K, int N, int Npad,
                                 const float* pa, const float* pb, int ksplit) {
    __shared__ float t[32][33];
    int bn = blockIdx.x * 32, bk = blockIdx.y * 32;
    int x = threadIdx.x, y = threadIdx.y;
#pragma unroll
    for (int j = 0; j < 32; j += 8) {
        int k = bk + y + j, n = bn + x;
        float v = (k < K && n < N) ? src[(size_t)k * N + n] : 0.f;
        if (pa) v *= (k < ksplit ? *pa : *pb);
        t[y + j][x] = v;
    }
    __syncthreads();
#pragma unroll
    for (int j = 0; j < 32; j += 8) {
        int n = bn + y + j, k = bk + x;
        if (n < Npad && k < K) dst[(size_t)n * K + k] = __float2half_rn(t[x][y + j]);
    }
}

__global__ void mean_init_kernel(const float* __restrict__ b) {
    int c = blockIdx.x * blockDim.x + threadIdx.x;
    if (c < NCLS) g_mean[c] = b[c];
}
__global__ void mean_part_kernel(const float* __restrict__ W) {
    int c = blockIdx.x * blockDim.x + threadIdx.x;
    if (c >= NCLS) return;
    int k0 = blockIdx.y * 64;
    float s = 0.f;
#pragma unroll 8
    for (int k = k0; k < k0 + 64; k++) s += W[(size_t)k * NCLS + c];
    atomicAdd(&g_mean[c], 0.5f * s);
}

// ============================================================
// K2: routed expert layer1 (fp16 MMA)
// ============================================================
__global__ __launch_bounds__(256) void expert1_h(
    const float* b10, const float* b11, const float* b12, const float* b13) {

    extern __shared__ char smem[];
    int e = blockIdx.z;
    int cnt = g_cnt[e];
    int row0 = blockIdx.x * BM;
    if (row0 >= cnt) return;

    int seg = 0;
#pragma unroll
    for (int q = 0; q < NE; q++) if (q < e) seg += g_cnt[q];

    const __half* Bts[4] = { g_w1t0, g_w1t1, g_w1t2, g_w1t3 };
    const float*  b1s[4] = { b10, b11, b12, b13 };
    const int     Ks[4]  = { 1536, 1536, 3072, 3072 };
    const int     Bs_[4] = { 0, 3, 0, 0 };
    const __half* Bt = Bts[e];
    const float*  b1 = b1s[e];
    int K = Ks[e];
    int base = Bs_[e];

    __shared__ int rowids[BM];
    int tid = threadIdx.x;
    for (int i = tid; i < BM; i += 256) {
        int r = row0 + i;
        rowids[i] = (r < cnt) ? g_rows[e * NB + r] : -1;
    }
    __syncthreads();

    int col0 = blockIdx.y * BN;
    int wid = tid >> 5, lane = tid & 31, g = lane >> 2, tg = lane & 3;
    int warpM = (wid & 3) * 32, warpN = (wid >> 2) * 64;
    int lr = tid >> 3, lc = tid & 7;

    float acc[2][8][4];
#pragma unroll
    for (int mi = 0; mi < 2; mi++)
#pragma unroll
        for (int ni = 0; ni < 8; ni++)
#pragma unroll
            for (int k = 0; k < 4; k++) acc[mi][ni][k] = 0.f;

    int ntiles = K / BK;

    auto prefetch = [&](int it) {
        int kc = it * BK;
        uint32_t sb = s2u(smem) + (it & 1) * STG_B;
#pragma unroll
        for (int t = 0; t < 4; t++) {
            int r = lr + t * 32;
            int rid = rowids[r];
            int kg = kc + lc * 8;
            int lraw = kg >> 9, d = kg & 511;
            const __half* src = g_xh + ((size_t)(lraw + base) * NB + (rid < 0 ? 0 : rid)) * DD + d;
            cp16(sb + r * RSTRB + lc * 16, src, rid >= 0 ? 16 : 0);
        }
#pragma unroll
        for (int t = 0; t < 4; t++) {
            int n = lr + t * 32;
            cp16(sb + TILE_BYTES + n * RSTRB + lc * 16,
                 Bt + (size_t)(col0 + n) * K + kc + lc * 8, 16);
        }
        cp_commit();
    };

    prefetch(0);
    for (int it = 0; it < ntiles; it++) {
        cp_wait0();
        __syncthreads();
        if (it + 1 < ntiles) prefetch(it + 1);
        const char* Ac = smem + (it & 1) * STG_B;
        tile_mma(Ac, Ac + TILE_BYTES, acc, warpM, warpN, g, tg);
        __syncthreads();
    }

#pragma unroll
    for (int mi = 0; mi < 2; mi++) {
        int ra = row0 + warpM + mi * 16 + g;
        int rb = ra + 8;
#pragma unroll
        for (int ni = 0; ni < 8; ni++) {
            int c0 = col0 + warpN + ni * 8 + tg * 2;
            float bb0 = b1[c0], bb1 = b1[c0 + 1];
            if (ra < cnt) {
                __half2 h = __floats2half2_rn(fmaxf(acc[mi][ni][0] + bb0, 0.f),
                                              fmaxf(acc[mi][ni][1] + bb1, 0.f));
                *(__half2*)(g_h + (size_t)(seg + ra) * DD + c0) = h;
            }
            if (rb < cnt) {
                __half2 h = __floats2half2_rn(fmaxf(acc[mi][ni][2] + bb0, 0.f),
                                              fmaxf(acc[mi][ni][3] + bb1, 0.f));
                *(__half2*)(g_h + (size_t)(seg + rb) * DD + c0) = h;
            }
        }
    }
}

// ============================================================
// K3: routed expert layer2 (fp16 MMA); scatter fp16 to g_s
// ============================================================
__global__ __launch_bounds__(256) void expert2_h(
    const float* b20, const float* b21, const float* b22, const float* b23) {

    extern __shared__ char smem[];
    int e = blockIdx.z;
    int cnt = g_cnt[e];
    int row0 = blockIdx.x * BM;
    if (row0 >= cnt) return;

    int seg = 0;
#pragma unroll
    for (int q = 0; q < NE; q++) if (q < e) seg += g_cnt[q];

    const __half* Bts[4] = { g_w2t0, g_w2t1, g_w2t2, g_w2t3 };
    const float*  b2s[4] = { b20, b21, b22, b23 };
    const __half* Bt = Bts[e];
    const float*  b2 = b2s[e];
    const int K = DD;

    __shared__ int rowids[BM];
    int tid = threadIdx.x;
    for (int i = tid; i < BM; i += 256) {
        int r = row0 + i;
        rowids[i] = (r < cnt) ? g_rows[e * NB + r] : -1;
    }
    __syncthreads();

    int col0 = blockIdx.y * BN;
    int wid = tid >> 5, lane = tid & 31, g = lane >> 2, tg = lane & 3;
    int warpM = (wid & 3) * 32, warpN = (wid >> 2) * 64;
    int lr = tid >> 3, lc = tid & 7;

    float acc[2][8][4];
#pragma unroll
    for (int mi = 0; mi < 2; mi++)
#pragma unroll
        for (int ni = 0; ni < 8; ni++)
#pragma unroll
            for (int k = 0; k < 4; k++) acc[mi][ni][k] = 0.f;

    const int ntiles = K / BK;

    auto prefetch = [&](int it) {
        int kc = it * BK;
        uint32_t sb = s2u(smem) + (it & 1) * STG_B;
#pragma unroll
        for (int t = 0; t < 4; t++) {
            int r = lr + t * 32;
            int ok = (row0 + r < cnt);
            cp16(sb + r * RSTRB + lc * 16,
                 g_h + (size_t)(seg + row0 + r) * DD + kc + lc * 8, ok ? 16 : 0);
        }
#pragma unroll
        for (int t = 0; t < 4; t++) {
            int n = lr + t * 32;
            cp16(sb + TILE_BYTES + n * RSTRB + lc * 16,
                 Bt + (size_t)(col0 + n) * K + kc + lc * 8, 16);
        }
        cp_commit();
    };

    prefetch(0);
    for (int it = 0; it < ntiles; it++) {
        cp_wait0();
        __syncthreads();
        if (it + 1 < ntiles) prefetch(it + 1);
        const char* Ac = smem + (it & 1) * STG_B;
        tile_mma(Ac, Ac + TILE_BYTES, acc, warpM, warpN, g, tg);
        __syncthreads();
    }

#pragma unroll
    for (int mi = 0; mi < 2; mi++) {
        int la = warpM + mi * 16 + g;
        int lb = la + 8;
        int rowa = rowids[la];
        int rowb = rowids[lb];
#pragma unroll
        for (int ni = 0; ni < 8; ni++) {
            int c0 = col0 + warpN + ni * 8 + tg * 2;
            float bb0 = b2[c0], bb1 = b2[c0 + 1];
            if (rowa >= 0) {
                __half2 h = __floats2half2_rn(acc[mi][ni][0] + bb0, acc[mi][ni][1] + bb1);
                *(__half2*)(g_s + (size_t)rowa * DD + c0) = h;
            }
            if (rowb >= 0) {
                __half2 h = __floats2half2_rn(acc[mi][ni][2] + bb0, acc[mi][ni][3] + bb1);
                *(__half2*)(g_s + (size_t)rowb * DD + c0) = h;
            }
        }
    }
}

// ============================================================
// K4: decoder layer1 (fp16 MMA); g_td = fp16(sigmoid-0.5)
// ============================================================
__global__ __launch_bounds__(256) void dec1_h(const float* __restrict__ bias) {
    extern __shared__ char smem[];
    int row0 = blockIdx.x * BM;
    int col0 = blockIdx.y * BN;
    int tid = threadIdx.x;
    int wid = tid >> 5, lane = tid & 31, g = lane >> 2, tg = lane & 3;
    int warpM = (wid & 3) * 32, warpN = (wid >> 2) * 64;
    int lr = tid >> 3, lc = tid & 7;

    float acc[2][8][4];
#pragma unroll
    for (int mi = 0; mi < 2; mi++)
#pragma unroll
        for (int ni = 0; ni < 8; ni++)
#pragma unroll
            for (int k = 0; k < 4; k++) acc[mi][ni][k] = 0.f;

    const int ntiles = DD / BK;

    auto prefetch = [&](int it) {
        int kc = it * BK;
        uint32_t sb = s2u(smem) + (it & 1) * STG_B;
#pragma unroll
        for (int t = 0; t < 4; t++) {
            int r = lr + t * 32;
            cp16(sb + r * RSTRB + lc * 16,
                 g_s + (size_t)(row0 + r) * DD + kc + lc * 8, 16);
        }
#pragma unroll
        for (int t = 0; t < 4; t++) {
            int n = lr + t * 32;
            cp16(sb + TILE_BYTES + n * RSTRB + lc * 16,
                 g_d1t + (size_t)(col0 + n) * DD + kc + lc * 8, 16);
        }
        cp_commit();
    };

    prefetch(0);
    for (int it = 0; it < ntiles; it++) {
        cp_wait0();
        __syncthreads();
        if (it + 1 < ntiles) prefetch(it + 1);
        const char* Ac = smem + (it & 1) * STG_B;
        tile_mma(Ac, Ac + TILE_BYTES, acc, warpM, warpN, g, tg);
        __syncthreads();
    }

#pragma unroll
    for (int mi = 0; mi < 2; mi++) {
        int ra = row0 + warpM + mi * 16 + g;
        int rb = ra + 8;
#pragma unroll
        for (int ni = 0; ni < 8; ni++) {
            int c0 = col0 + warpN + ni * 8 + tg * 2;
            float bb0 = bias[c0], bb1 = bias[c0 + 1];
            float z0 = 1.f / (1.f + expf(-(acc[mi][ni][0] + bb0))) - 0.5f;
            float z1 = 1.f / (1.f + expf(-(acc[mi][ni][1] + bb1))) - 0.5f;
            float z2 = 1.f / (1.f + expf(-(acc[mi][ni][2] + bb0))) - 0.5f;
            float z3 = 1.f / (1.f + expf(-(acc[mi][ni][3] + bb1))) - 0.5f;
            *(__half2*)(g_td + (size_t)ra * DD + c0) = __floats2half2_rn(z0, z1);
            *(__half2*)(g_td + (size_t)rb * DD + c0) = __floats2half2_rn(z2, z3);
        }
    }
}

// ============================================================
// K5: decoder layer2 (fp16 MMA) on delta; out = acc + mean[c]
// ============================================================
__global__ __launch_bounds__(256) void dec2_h(float* __restrict__ out) {
    extern __shared__ char smem[];
    int row0 = blockIdx.x * BM;
    int col0 = blockIdx.y * BN;
    int tid = threadIdx.x;
    int wid = tid >> 5, lane = tid & 31, g = lane >> 2, tg = lane & 3;
    int warpM = (wid & 3) * 32, warpN = (wid >> 2) * 64;
    int lr = tid >> 3, lc = tid & 7;

    float acc[2][8][4];
#pragma unroll
    for (int mi = 0; mi < 2; mi++)
#pragma unroll
        for (int ni = 0; ni < 8; ni++)
#pragma unroll
            for (int k = 0; k < 4; k++) acc[mi][ni][k] = 0.f;

    const int ntiles = DD / BK;

    auto prefetch = [&](int it) {
        int kc = it * BK;
        uint32_t sb = s2u(smem) + (it & 1) * STG_B;
#pragma unroll
        for (int t = 0; t < 4; t++) {
            int r = lr + t * 32;
            cp16(sb + r * RSTRB + lc * 16,
                 g_td + (size_t)(row0 + r) * DD + kc + lc * 8, 16);
        }
#pragma unroll
        for (int t = 0; t < 4; t++) {
            int n = lr + t * 32;
            cp16(sb + TILE_BYTES + n * RSTRB + lc * 16,
                 g_d2t + (size_t)(col0 + n) * DD + kc + lc * 8, 16);
        }
        cp_commit();
    };

    prefetch(0);
    for (int it = 0; it < ntiles; it++) {
        cp_wait0();
        __syncthreads();
        if (it + 1 < ntiles) prefetch(it + 1);
        const char* Ac = smem + (it & 1) * STG_B;
        tile_mma(Ac, Ac + TILE_BYTES, acc, warpM, warpN, g, tg);
        __syncthreads();
    }

#pragma unroll
    for (int mi = 0; mi < 2; mi++) {
        int ra = row0 + warpM + mi * 16 + g;
        int rb = ra + 8;
#pragma unroll
        for (int ni = 0; ni < 8; ni++) {
            int c0 = col0 + warpN + ni * 8 + tg * 2;
            int c1 = c0 + 1;
            if (c0 < NCLS) {
                float m0 = g_mean[c0];
                out[(size_t)ra * NCLS + c0] = acc[mi][ni][0] + m0;
                out[(size_t)rb * NCLS + c0] = acc[mi][ni][2] + m0;
            }
            if (c1 < NCLS) {
                float m1 = g_mean[c1];
                out[(size_t)ra * NCLS + c1] = acc[mi][ni][1] + m1;
                out[(size_t)rb * NCLS + c1] = acc[mi][ni][3] + m1;
            }
        }
    }
}

// ============================================================
// launch — fork-join graph branches for prep
// ============================================================
extern "C" void kernel_launch(void* const* d_in, const int* in_sizes, int n_in,
                              void* d_out, int out_size) {
    const float* fusion = (const float*)d_in[0];
    const float* gate_W = (const float*)d_in[1];
    const float* gate_b = (const float*)d_in[2];
    const float* e0_W1  = (const float*)d_in[3];
    const float* e0_b1  = (const float*)d_in[4];
    const float* e0_W2  = (const float*)d_in[5];
    const float* e0_b2  = (const float*)d_in[6];
    const float* e1_W1  = (const float*)d_in[7];
    const float* e1_b1  = (const float*)d_in[8];
    const float* e1_W2  = (const float*)d_in[9];
    const float* e1_b2  = (const float*)d_in[10];
    const float* e2_W1  = (const float*)d_in[11];
    const float* e2_b1  = (const float*)d_in[12];
    const float* e2_W2  = (const float*)d_in[13];
    const float* e2_b2  = (const float*)d_in[14];
    const float* e3_W1  = (const float*)d_in[15];
    const float* e3_b1  = (const float*)d_in[16];
    const float* e3_W2  = (const float*)d_in[17];
    const float* e3_b2  = (const float*)d_in[18];
    const float* e3_a   = (const float*)d_in[19];
    const float* e3_b   = (const float*)d_in[20];
    const float* dec_W1 = (const float*)d_in[21];
    const float* dec_b1 = (const float*)d_in[22];
    const float* dec_W2 = (const float*)d_in[23];
    const float* dec_b2 = (const float*)d_in[24];
    float* out = (float*)d_out;

    static bool init_done = false;
    static cudaStream_t sA, sB, sC;
    static cudaEvent_t evRoot, evA, evB, evC;
    if (!init_done) {
        cudaFuncSetAttribute(expert1_h, cudaFuncAttributeMaxDynamicSharedMemorySize, SMEM_BYTES);
        cudaFuncSetAttribute(expert2_h, cudaFuncAttributeMaxDynamicSharedMemorySize, SMEM_BYTES);
        cudaFuncSetAttribute(dec1_h,    cudaFuncAttributeMaxDynamicSharedMemorySize, SMEM_BYTES);
        cudaFuncSetAttribute(dec2_h,    cudaFuncAttributeMaxDynamicSharedMemorySize, SMEM_BYTES);
        cudaStreamCreateWithFlags(&sA, cudaStreamNonBlocking);
        cudaStreamCreateWithFlags(&sB, cudaStreamNonBlocking);
        cudaStreamCreateWithFlags(&sC, cudaStreamNonBlocking);
        cudaEventCreateWithFlags(&evRoot, cudaEventDisableTiming);
        cudaEventCreateWithFlags(&evA, cudaEventDisableTiming);
        cudaEventCreateWithFlags(&evB, cudaEventDisableTiming);
        cudaEventCreateWithFlags(&evC, cudaEventDisableTiming);
        init_done = true;
    }

    __half* w1t0; cudaGetSymbolAddress((void**)&w1t0, g_w1t0);
    __half* w1t1; cudaGetSymbolAddress((void**)&w1t1, g_w1t1);
    __half* w1t2; cudaGetSymbolAddress((void**)&w1t2, g_w1t2);
    __half* w1t3; cudaGetSymbolAddress((void**)&w1t3, g_w1t3);
    __half* w2t0; cudaGetSymbolAddress((void**)&w2t0, g_w2t0);
    __half* w2t1; cudaGetSymbolAddress((void**)&w2t1, g_w2t1);
    __half* w2t2; cudaGetSymbolAddress((void**)&w2t2, g_w2t2);
    __half* w2t3; cudaGetSymbolAddress((void**)&w2t3, g_w2t3);
    __half* d1t;  cudaGetSymbolAddress((void**)&d1t,  g_d1t);
    __half* d2t;  cudaGetSymbolAddress((void**)&d2t,  g_d2t);

    // ---- fork ----
    cudaEventRecord(evRoot, 0);
    cudaStreamWaitEvent(sA, evRoot, 0);
    cudaStreamWaitEvent(sB, evRoot, 0);
    cudaStreamWaitEvent(sC, evRoot, 0);

    // stream 0: gate -> compact
    gate_kernel<<<NB / 4, 128>>>(fusion, gate_W, gate_b);
    zero_cnt_kernel<<<1, 32>>>();
    compact_kernel<<<NB / 256, 256>>>();

    // sA: fp16 conversion of fusion
    conv_fusion_kernel<<<(NL * NB * DD / 4) / 256, 256, 0, sA>>>(fusion);

    // sB: expert weight transposes (needed by expert1/expert2)
    {
        dim3 blk(32, 8);
        transpose_kernel<<<dim3(16, 48), blk, 0, sB>>>(e0_W1, w1t0, 1536, 512, 512, 0, 0, 0);
        transpose_kernel<<<dim3(16, 48), blk, 0, sB>>>(e1_W1, w1t1, 1536, 512, 512, 0, 0, 0);
        transpose_kernel<<<dim3(16, 96), blk, 0, sB>>>(e2_W1, w1t2, 3072, 512, 512, 0, 0, 0);
        transpose_kernel<<<dim3(16, 96), blk, 0, sB>>>(e3_W1, w1t3, 3072, 512, 512, e3_a, e3_b, 1536);
        transpose_kernel<<<dim3(16, 16), blk, 0, sB>>>(e0_W2, w2t0, 512, 512, 512, 0, 0, 0);
        transpose_kernel<<<dim3(16, 16), blk, 0, sB>>>(e1_W2, w2t1, 512, 512, 512, 0, 0, 0);
        transpose_kernel<<<dim3(16, 16), blk, 0, sB>>>(e2_W2, w2t2, 512, 512, 512, 0, 0, 0);
        transpose_kernel<<<dim3(16, 16), blk, 0, sB>>>(e3_W2, w2t3, 512, 512, 512, 0, 0, 0);
    }

    // sC: decoder-side transposes + mean (only needed by dec1/dec2;
    //     hidden under expert GEMMs)
    {
        dim3 blk(32, 8);
        transpose_kernel<<<dim3(16, 16), blk, 0, sC>>>(dec_W1, d1t, 512, 512, 512, 0, 0, 0);
        transpose_kernel<<<dim3(128, 16), blk, 0, sC>>>(dec_W2, d2t, 512, 3992, 4096, 0, 0, 0);
        mean_init_kernel<<<(NCLS + 255) / 256, 256, 0, sC>>>(dec_b2);
        dim3 grid((NCLS + 255) / 256, DD / 64);
        mean_part_kernel<<<grid, 256, 0, sC>>>(dec_W2);
    }

    cudaEventRecord(evA, sA);
    cudaEventRecord(evB, sB);
    cudaEventRecord(evC, sC);

    // ---- join A,B before expert GEMMs ----
    cudaStreamWaitEvent(0, evA, 0);
    cudaStreamWaitEvent(0, evB, 0);

    {
        dim3 grid(NB / BM, DD / BN, NE);
        expert1_h<<<grid, 256, SMEM_BYTES>>>(e0_b1, e1_b1, e2_b1, e3_b1);
    }
    {
        dim3 grid(NB / BM, DD / BN, NE);
        expert2_h<<<grid, 256, SMEM_BYTES>>>(e0_b2, e1_b2, e2_b2, e3_b2);
    }

    // ---- join C before decoder ----
    cudaStreamWaitEvent(0, evC, 0);

    {
        dim3 grid(NB / BM, DD / BN);
        dec1_h<<<grid, 256, SMEM_BYTES>>>(dec_b1);
    }
    {
        dim3 grid(NB / BM, (NCLS + BN - 1) / BN);
        dec2_h<<<grid, 256, SMEM_BYTES>>>(out);
    }
}